// round 2
// baseline (speedup 1.0000x reference)
#include <cuda_runtime.h>
#include <cuda_bf16.h>
#include <cstddef>

// Problem constants
#define B_   2
#define S_   2048
#define DM_  1024
#define H_   16
#define DK_  64
#define M_   (B_ * S_)             // 4096 rows
#define OUT_ELEMS  ((long long)M_ * DM_)                 // 4,194,304
#define ATTN_ELEMS ((long long)B_ * H_ * S_ * S_)        // 134,217,728

// ---------------- scratch (device globals: the sanctioned workaround) ----------------
__device__ float g_Q[M_ * DM_];
__device__ float g_K[M_ * DM_];
__device__ float g_V[M_ * DM_];
__device__ float g_ctx[M_ * DM_];
__device__ float g_y[M_ * DM_];
__device__ float g_attn[(size_t)B_ * H_ * S_ * S_];   // fallback if attn not in d_out
__device__ int   g_maskmode;                          // 0=uint8, 1=int32, 2=float32

// =====================================================================
// Mask storage-format detection: scan first 64KB, classify by which
// byte lanes (idx & 3) carry nonzero bytes.
//   uint8 bool 0/1 : nonzero bytes at all lanes (incl. lane 1)
//   int32 0/1      : nonzero only at lane 0 (little-endian LSB)
//   float32 0/1    : 1.0f = 00 00 80 3F -> nonzero only at lanes 2,3
// =====================================================================
__global__ void detect_mask_kernel(const unsigned char* __restrict__ m)
{
    __shared__ int cnt[4];
    if (threadIdx.x < 4) cnt[threadIdx.x] = 0;
    __syncthreads();
    for (int i = threadIdx.x; i < 65536; i += blockDim.x)
        if (m[i]) atomicAdd(&cnt[i & 3], 1);
    __syncthreads();
    if (threadIdx.x == 0) {
        int mode;
        if (cnt[1] > 0)      mode = 0;   // bool bytes
        else if (cnt[0] > 0) mode = 1;   // int32
        else                 mode = 2;   // float32
        g_maskmode = mode;
    }
}

// =====================================================================
// SGEMM: C[M,N] = A[M,K] @ B[K,N] (+ Res), fp32, 128x128x8, 8x8 micro
// =====================================================================
__global__ __launch_bounds__(256) void sgemm128(
    const float* __restrict__ A, const float* __restrict__ Bm,
    const float* __restrict__ Res, float* __restrict__ C,
    int M, int N, int K)
{
    __shared__ float As[8][132];   // [k][m], padded
    __shared__ float Bs[8][128];   // [k][n]

    const int tid  = threadIdx.x;
    const int tx   = tid & 15;     // n group
    const int ty   = tid >> 4;     // m group
    const int row0 = blockIdx.y * 128;
    const int col0 = blockIdx.x * 128;

    const int arow = tid >> 1;         // 0..127
    const int acol = (tid & 1) * 4;    // 0 or 4
    const int brow = tid >> 5;         // 0..7
    const int bcol = (tid & 31) * 4;   // 0..124

    float acc[8][8];
#pragma unroll
    for (int i = 0; i < 8; i++)
#pragma unroll
        for (int j = 0; j < 8; j++) acc[i][j] = 0.f;

    for (int kt = 0; kt < K; kt += 8) {
        float4 a = *(const float4*)&A[(size_t)(row0 + arow) * K + kt + acol];
        As[acol + 0][arow] = a.x;
        As[acol + 1][arow] = a.y;
        As[acol + 2][arow] = a.z;
        As[acol + 3][arow] = a.w;
        *(float4*)&Bs[brow][bcol] =
            *(const float4*)&Bm[(size_t)(kt + brow) * N + col0 + bcol];
        __syncthreads();

#pragma unroll
        for (int k = 0; k < 8; ++k) {
            float4 a0 = *(const float4*)&As[k][ty * 8];
            float4 a1 = *(const float4*)&As[k][ty * 8 + 4];
            float4 b0 = *(const float4*)&Bs[k][tx * 8];
            float4 b1 = *(const float4*)&Bs[k][tx * 8 + 4];
            float am[8] = {a0.x, a0.y, a0.z, a0.w, a1.x, a1.y, a1.z, a1.w};
            float bn[8] = {b0.x, b0.y, b0.z, b0.w, b1.x, b1.y, b1.z, b1.w};
#pragma unroll
            for (int i = 0; i < 8; i++)
#pragma unroll
                for (int j = 0; j < 8; j++) acc[i][j] += am[i] * bn[j];
        }
        __syncthreads();
    }

#pragma unroll
    for (int i = 0; i < 8; i++) {
        int r = row0 + ty * 8 + i;
#pragma unroll
        for (int j = 0; j < 8; j++) {
            int c = col0 + tx * 8 + j;
            float v = acc[i][j];
            if (Res) v += Res[(size_t)r * N + c];
            C[(size_t)r * N + c] = v;
        }
    }
}

// =====================================================================
// Scores: attn[bh, q, k] = (Q_h q · K_h k) / 8, masked with -1e9
// =====================================================================
__global__ __launch_bounds__(256) void scores_kernel(
    const float* __restrict__ Q, const float* __restrict__ Kp,
    const unsigned char* __restrict__ mask_u8, float* __restrict__ attn)
{
    __shared__ float Qt[64][68];   // [d][q]
    __shared__ float Kt[64][68];   // [d][k]

    const int bh = blockIdx.z;
    const int b  = bh >> 4;
    const int h  = bh & 15;
    const int q0 = blockIdx.y * 64;
    const int k0 = blockIdx.x * 64;
    const int tid = threadIdx.x;
    const int mode = g_maskmode;
    const int*   mask_i32 = (const int*)mask_u8;
    const float* mask_f32 = (const float*)mask_u8;

    for (int i = tid; i < 64 * 16; i += 256) {
        int r  = i >> 4;           // row within tile
        int d4 = (i & 15) * 4;     // d offset
        float4 qv = *(const float4*)&Q[((size_t)(b * S_ + q0 + r)) * DM_ + h * DK_ + d4];
        Qt[d4 + 0][r] = qv.x; Qt[d4 + 1][r] = qv.y;
        Qt[d4 + 2][r] = qv.z; Qt[d4 + 3][r] = qv.w;
        float4 kv = *(const float4*)&Kp[((size_t)(b * S_ + k0 + r)) * DM_ + h * DK_ + d4];
        Kt[d4 + 0][r] = kv.x; Kt[d4 + 1][r] = kv.y;
        Kt[d4 + 2][r] = kv.z; Kt[d4 + 3][r] = kv.w;
    }
    __syncthreads();

    const int tx = tid & 15;   // k group
    const int ty = tid >> 4;   // q group
    float acc[4][4];
#pragma unroll
    for (int i = 0; i < 4; i++)
#pragma unroll
        for (int j = 0; j < 4; j++) acc[i][j] = 0.f;

#pragma unroll
    for (int d = 0; d < 64; ++d) {
        float4 qv = *(const float4*)&Qt[d][ty * 4];
        float4 kv = *(const float4*)&Kt[d][tx * 4];
        float qm[4] = {qv.x, qv.y, qv.z, qv.w};
        float kn[4] = {kv.x, kv.y, kv.z, kv.w};
#pragma unroll
        for (int i = 0; i < 4; i++)
#pragma unroll
            for (int j = 0; j < 4; j++) acc[i][j] += qm[i] * kn[j];
    }

#pragma unroll
    for (int i = 0; i < 4; i++) {
        int qg = q0 + ty * 4 + i;
#pragma unroll
        for (int j = 0; j < 4; j++) {
            int kg = k0 + tx * 4 + j;
            float s = acc[i][j] * 0.125f;
            size_t midx = ((size_t)b * S_ + qg) * S_ + kg;
            bool masked;
            if (mode == 0)      masked = mask_u8[midx] != 0;
            else if (mode == 1) masked = mask_i32[midx] != 0;
            else                masked = mask_f32[midx] != 0.0f;
            attn[((size_t)bh * S_ + qg) * S_ + kg] = masked ? -1e9f : s;
        }
    }
}

// =====================================================================
// Row softmax over 2048 elements, one block per row
// =====================================================================
__global__ __launch_bounds__(256) void softmax_kernel(float* __restrict__ attn)
{
    const int tid = threadIdx.x;
    float* p = attn + (size_t)blockIdx.x * S_;
    const int warp = tid >> 5, lane = tid & 31;
    __shared__ float red[8];

    float v[8];
#pragma unroll
    for (int j = 0; j < 8; j++) v[j] = p[tid + j * 256];

    float m = v[0];
#pragma unroll
    for (int j = 1; j < 8; j++) m = fmaxf(m, v[j]);
#pragma unroll
    for (int o = 16; o > 0; o >>= 1) m = fmaxf(m, __shfl_xor_sync(0xffffffffu, m, o));
    if (lane == 0) red[warp] = m;
    __syncthreads();
    if (tid == 0) {
        float t = red[0];
#pragma unroll
        for (int w = 1; w < 8; w++) t = fmaxf(t, red[w]);
        red[0] = t;
    }
    __syncthreads();
    m = red[0];

    float s = 0.f;
#pragma unroll
    for (int j = 0; j < 8; j++) { v[j] = __expf(v[j] - m); s += v[j]; }
#pragma unroll
    for (int o = 16; o > 0; o >>= 1) s += __shfl_xor_sync(0xffffffffu, s, o);
    __syncthreads();
    if (lane == 0) red[warp] = s;
    __syncthreads();
    if (tid == 0) {
        float t = 0.f;
#pragma unroll
        for (int w = 0; w < 8; w++) t += red[w];
        red[0] = t;
    }
    __syncthreads();
    float inv = 1.0f / red[0];

#pragma unroll
    for (int j = 0; j < 8; j++) p[tid + j * 256] = v[j] * inv;
}

// =====================================================================
// Context: ctx[b,q,h*64+dv] = sum_k attn[bh,q,k] * V[b,k,h*64+dv]
// =====================================================================
__global__ __launch_bounds__(256) void ctx_kernel(
    const float* __restrict__ attn, const float* __restrict__ V,
    float* __restrict__ ctx)
{
    __shared__ float At[64][68];   // [k][q]
    __shared__ float Vs[64][68];   // [k][dv]

    const int bh = blockIdx.y;
    const int b  = bh >> 4;
    const int h  = bh & 15;
    const int q0 = blockIdx.x * 64;
    const int tid = threadIdx.x;
    const int tx = tid & 15;   // dv group
    const int ty = tid >> 4;   // q group

    float acc[4][4];
#pragma unroll
    for (int i = 0; i < 4; i++)
#pragma unroll
        for (int j = 0; j < 4; j++) acc[i][j] = 0.f;

    for (int kt = 0; kt < S_; kt += 64) {
        for (int i = tid; i < 64 * 16; i += 256) {
            int r  = i >> 4;
            int c4 = (i & 15) * 4;
            float4 av = *(const float4*)&attn[((size_t)bh * S_ + q0 + r) * S_ + kt + c4];
            At[c4 + 0][r] = av.x; At[c4 + 1][r] = av.y;
            At[c4 + 2][r] = av.z; At[c4 + 3][r] = av.w;
            float4 vv = *(const float4*)&V[((size_t)(b * S_ + kt + r)) * DM_ + h * DK_ + c4];
            *(float4*)&Vs[r][c4] = vv;
        }
        __syncthreads();

#pragma unroll
        for (int k = 0; k < 64; ++k) {
            float4 av = *(const float4*)&At[k][ty * 4];
            float4 vv = *(const float4*)&Vs[k][tx * 4];
            float am[4] = {av.x, av.y, av.z, av.w};
            float vn[4] = {vv.x, vv.y, vv.z, vv.w};
#pragma unroll
            for (int i = 0; i < 4; i++)
#pragma unroll
                for (int j = 0; j < 4; j++) acc[i][j] += am[i] * vn[j];
        }
        __syncthreads();
    }

#pragma unroll
    for (int i = 0; i < 4; i++) {
        int qg = q0 + ty * 4 + i;
#pragma unroll
        for (int j = 0; j < 4; j++) {
            int dv = tx * 4 + j;
            ctx[((size_t)(b * S_ + qg)) * DM_ + h * DK_ + dv] = acc[i][j];
        }
    }
}

// =====================================================================
// LayerNorm over last dim (1024), gamma=1 beta=0, one block per row
// =====================================================================
__global__ __launch_bounds__(256) void ln_kernel(
    const float* __restrict__ y, float* __restrict__ out)
{
    const int tid = threadIdx.x;
    const float* p = y + (size_t)blockIdx.x * DM_;
    float* o = out + (size_t)blockIdx.x * DM_;
    const int warp = tid >> 5, lane = tid & 31;
    __shared__ float red[8];

    float v[4];
#pragma unroll
    for (int j = 0; j < 4; j++) v[j] = p[tid + j * 256];

    float s = v[0] + v[1] + v[2] + v[3];
#pragma unroll
    for (int o2 = 16; o2 > 0; o2 >>= 1) s += __shfl_xor_sync(0xffffffffu, s, o2);
    if (lane == 0) red[warp] = s;
    __syncthreads();
    if (tid == 0) {
        float t = 0.f;
#pragma unroll
        for (int w = 0; w < 8; w++) t += red[w];
        red[0] = t;
    }
    __syncthreads();
    float mu = red[0] * (1.0f / DM_);

    float sq = 0.f;
#pragma unroll
    for (int j = 0; j < 4; j++) { float d = v[j] - mu; sq += d * d; }
#pragma unroll
    for (int o2 = 16; o2 > 0; o2 >>= 1) sq += __shfl_xor_sync(0xffffffffu, sq, o2);
    __syncthreads();
    if (lane == 0) red[warp] = sq;
    __syncthreads();
    if (tid == 0) {
        float t = 0.f;
#pragma unroll
        for (int w = 0; w < 8; w++) t += red[w];
        red[0] = t;
    }
    __syncthreads();
    float inv = rsqrtf(red[0] * (1.0f / DM_) + 1e-5f);

#pragma unroll
    for (int j = 0; j < 4; j++) o[tid + j * 256] = (v[j] - mu) * inv;
}

// =====================================================================
// Launch
// =====================================================================
extern "C" void kernel_launch(void* const* d_in, const int* in_sizes, int n_in,
                              void* d_out, int out_size)
{
    const float* inQ = (const float*)d_in[0];
    const float* inK = (const float*)d_in[1];
    const float* inV = (const float*)d_in[2];
    const unsigned char* mask = (const unsigned char*)d_in[3];
    const float* WQ = (const float*)d_in[4];
    const float* WK = (const float*)d_in[5];
    const float* WV = (const float*)d_in[6];
    const float* WO = (const float*)d_in[7];
    float* out = (float*)d_out;

    float *Qp, *Kp, *Vp, *Cp, *Yp, *Ap;
    cudaGetSymbolAddress((void**)&Qp, g_Q);
    cudaGetSymbolAddress((void**)&Kp, g_K);
    cudaGetSymbolAddress((void**)&Vp, g_V);
    cudaGetSymbolAddress((void**)&Cp, g_ctx);
    cudaGetSymbolAddress((void**)&Yp, g_y);
    cudaGetSymbolAddress((void**)&Ap, g_attn);

    // If d_out holds both returns (out, attn), write attn straight into it.
    float* attn = ((long long)out_size >= OUT_ELEMS + ATTN_ELEMS) ? (out + OUT_ELEMS) : Ap;

    detect_mask_kernel<<<1, 256>>>(mask);

    dim3 gemm_grid(DM_ / 128, M_ / 128);   // (8, 32)

    sgemm128<<<gemm_grid, 256>>>(inQ, WQ, nullptr, Qp, M_, DM_, DM_);
    sgemm128<<<gemm_grid, 256>>>(inK, WK, nullptr, Kp, M_, DM_, DM_);
    sgemm128<<<gemm_grid, 256>>>(inV, WV, nullptr, Vp, M_, DM_, DM_);

    scores_kernel<<<dim3(S_ / 64, S_ / 64, B_ * H_), 256>>>(Qp, Kp, mask, attn);
    softmax_kernel<<<B_ * H_ * S_, 256>>>(attn);
    ctx_kernel<<<dim3(S_ / 64, B_ * H_), 256>>>(attn, Vp, Cp);

    sgemm128<<<gemm_grid, 256>>>(Cp, WO, inQ, Yp, M_, DM_, DM_);
    ln_kernel<<<M_, 256>>>(Yp, out);
}

// round 4
// speedup vs baseline: 1.2799x; 1.2799x over previous
#include <cuda_runtime.h>
#include <cuda_bf16.h>
#include <cstddef>
#include <cstdint>

// Problem constants
#define B_   2
#define S_   2048
#define DM_  1024
#define H_   16
#define DK_  64
#define M_   (B_ * S_)             // 4096 rows
#define OUT_ELEMS  ((long long)M_ * DM_)                 // 4,194,304
#define ATTN_ELEMS ((long long)B_ * H_ * S_ * S_)        // 134,217,728

// ---------------- scratch (device globals) ----------------
__device__ float g_Q[M_ * DM_];
__device__ float g_K[M_ * DM_];
__device__ float g_V[M_ * DM_];
__device__ float g_ctx[M_ * DM_];
__device__ float g_y[M_ * DM_];
__device__ float g_attn[(size_t)B_ * H_ * S_ * S_];
__device__ int   g_maskmode;   // 0=uint8, 1=int32, 2=float32

// =====================================================================
// Mask storage-format detection (proven)
// =====================================================================
__global__ void detect_mask_kernel(const unsigned char* __restrict__ m)
{
    __shared__ int cnt[4];
    if (threadIdx.x < 4) cnt[threadIdx.x] = 0;
    __syncthreads();
    for (int i = threadIdx.x; i < 65536; i += blockDim.x)
        if (m[i]) atomicAdd(&cnt[i & 3], 1);
    __syncthreads();
    if (threadIdx.x == 0) {
        int mode;
        if (cnt[1] > 0)      mode = 0;
        else if (cnt[0] > 0) mode = 1;
        else                 mode = 2;
        g_maskmode = mode;
    }
}

// =====================================================================
// mma.sync helpers (sm_80+ path — legal on plain sm_103 target)
// =====================================================================
__device__ __forceinline__ void ldsm_x4(uint32_t* r, uint32_t addr) {
    asm volatile("ldmatrix.sync.aligned.m8n8.x4.shared.b16 {%0,%1,%2,%3}, [%4];"
                 : "=r"(r[0]), "=r"(r[1]), "=r"(r[2]), "=r"(r[3]) : "r"(addr));
}
__device__ __forceinline__ void ldsm_x4t(uint32_t* r, uint32_t addr) {
    asm volatile("ldmatrix.sync.aligned.m8n8.x4.trans.shared.b16 {%0,%1,%2,%3}, [%4];"
                 : "=r"(r[0]), "=r"(r[1]), "=r"(r[2]), "=r"(r[3]) : "r"(addr));
}
__device__ __forceinline__ void mma_bf16(float* c, const uint32_t* a, const uint32_t* b) {
    asm volatile(
        "mma.sync.aligned.m16n8k16.row.col.f32.bf16.bf16.f32 "
        "{%0,%1,%2,%3}, {%4,%5,%6,%7}, {%8,%9}, {%0,%1,%2,%3};"
        : "+f"(c[0]), "+f"(c[1]), "+f"(c[2]), "+f"(c[3])
        : "r"(a[0]), "r"(a[1]), "r"(a[2]), "r"(a[3]), "r"(b[0]), "r"(b[1]));
}

__device__ __forceinline__ void split_bf16(float x, __nv_bfloat16& h, __nv_bfloat16& l) {
    h = __float2bfloat16_rn(x);
    l = __float2bfloat16_rn(x - __bfloat162float(h));
}

// =====================================================================
// mma.sync split-bf16 GEMM: C[4096,1024] = A[4096,1024]@B[1024,1024] (+Res)
// Block tile 128(M)x64(N), 8 warps (4x2), warp tile 32x32, K-chunk 64.
// smem rows padded to 72 elements (stride 144B = 36 words): each ldmatrix
// 8-row tile covers banks {4r..4r+3 mod 32} = all 32 banks, conflict-free.
// =====================================================================
#define PADK 72
#define SM_AH 0
#define SM_AL (128 * PADK * 2)
#define SM_BH (2 * 128 * PADK * 2)
#define SM_BL (2 * 128 * PADK * 2 + 64 * PADK * 2)
#define MMA_SMEM_BYTES (2 * 128 * PADK * 2 + 2 * 64 * PADK * 2)   // 55296

__global__ __launch_bounds__(256) void mma_gemm(
    const float* __restrict__ A, const float* __restrict__ Bm,
    const float* __restrict__ Res, float* __restrict__ C)
{
    extern __shared__ __align__(16) char dsm[];
    const uint32_t sbase = (uint32_t)__cvta_generic_to_shared(dsm);

    const int tid  = threadIdx.x;
    const int lane = tid & 31;
    const int warp = tid >> 5;
    const int wm   = warp & 3;    // 4 M-tiles of 32
    const int wn   = warp >> 2;   // 2 N-tiles of 32
    const int row0 = blockIdx.y * 128;
    const int n0   = blockIdx.x * 64;

    float acc[2][4][4];
#pragma unroll
    for (int i = 0; i < 2; i++)
#pragma unroll
        for (int j = 0; j < 4; j++)
#pragma unroll
            for (int k = 0; k < 4; k++) acc[i][j][k] = 0.f;

    // ldmatrix per-lane element offsets (A: [m][k] row-major; B: [k][n] row-major)
    uint32_t aoff[2], boff[2];
#pragma unroll
    for (int mi = 0; mi < 2; ++mi)
        aoff[mi] = (uint32_t)((wm * 32 + mi * 16 + (lane & 15)) * PADK + (lane >> 4) * 8);
#pragma unroll
    for (int njp = 0; njp < 2; ++njp)
        boff[njp] = (uint32_t)((((lane >> 3) & 1) * 8 + (lane & 7)) * PADK
                               + wn * 32 + njp * 16 + (lane >> 4) * 8);

    for (int c = 0; c < DM_ / 64; ++c) {
        const int k0 = c * 64;

        // ---- global loads (registers) ----
        float4 av[8];
#pragma unroll
        for (int i = 0; i < 8; ++i) {
            int idx = tid + i * 256;
            int r  = idx >> 4;
            int kc = (idx & 15) * 4;
            av[i] = *(const float4*)&A[(size_t)(row0 + r) * DM_ + k0 + kc];
        }
        float4 bv[4];
#pragma unroll
        for (int i = 0; i < 4; ++i) {
            int idx = tid + i * 256;
            int kr = idx >> 4;
            int nc = (idx & 15) * 4;
            bv[i] = *(const float4*)&Bm[(size_t)(k0 + kr) * DM_ + n0 + nc];
        }

        if (c > 0) __syncthreads();   // protect previous chunk's smem reads

        // ---- convert + store hi/lo to smem ----
#pragma unroll
        for (int i = 0; i < 8; ++i) {
            int idx = tid + i * 256;
            int r  = idx >> 4;
            int kc = (idx & 15) * 4;
            uint32_t eo = (uint32_t)(r * PADK + kc) * 2;
            __nv_bfloat16 h0, h1, h2, h3, l0, l1, l2, l3;
            split_bf16(av[i].x, h0, l0); split_bf16(av[i].y, h1, l1);
            split_bf16(av[i].z, h2, l2); split_bf16(av[i].w, h3, l3);
            *(__nv_bfloat162*)(dsm + SM_AH + eo)     = __halves2bfloat162(h0, h1);
            *(__nv_bfloat162*)(dsm + SM_AH + eo + 4) = __halves2bfloat162(h2, h3);
            *(__nv_bfloat162*)(dsm + SM_AL + eo)     = __halves2bfloat162(l0, l1);
            *(__nv_bfloat162*)(dsm + SM_AL + eo + 4) = __halves2bfloat162(l2, l3);
        }
#pragma unroll
        for (int i = 0; i < 4; ++i) {
            int idx = tid + i * 256;
            int kr = idx >> 4;
            int nc = (idx & 15) * 4;
            uint32_t eo = (uint32_t)(kr * PADK + nc) * 2;
            __nv_bfloat16 h0, h1, h2, h3, l0, l1, l2, l3;
            split_bf16(bv[i].x, h0, l0); split_bf16(bv[i].y, h1, l1);
            split_bf16(bv[i].z, h2, l2); split_bf16(bv[i].w, h3, l3);
            *(__nv_bfloat162*)(dsm + SM_BH + eo)     = __halves2bfloat162(h0, h1);
            *(__nv_bfloat162*)(dsm + SM_BH + eo + 4) = __halves2bfloat162(h2, h3);
            *(__nv_bfloat162*)(dsm + SM_BL + eo)     = __halves2bfloat162(l0, l1);
            *(__nv_bfloat162*)(dsm + SM_BL + eo + 4) = __halves2bfloat162(l2, l3);
        }
        __syncthreads();

        // ---- 4 k-steps of 16 ----
#pragma unroll
        for (int ks = 0; ks < 4; ++ks) {
            uint32_t ah[2][4], al[2][4], bh[2][4], bl[2][4];
#pragma unroll
            for (int mi = 0; mi < 2; ++mi) {
                uint32_t eo = (aoff[mi] + ks * 16) * 2;
                ldsm_x4(ah[mi], sbase + SM_AH + eo);
                ldsm_x4(al[mi], sbase + SM_AL + eo);
            }
#pragma unroll
            for (int njp = 0; njp < 2; ++njp) {
                uint32_t eo = (boff[njp] + ks * 16 * PADK) * 2;
                ldsm_x4t(bh[njp], sbase + SM_BH + eo);
                ldsm_x4t(bl[njp], sbase + SM_BL + eo);
            }
#pragma unroll
            for (int mi = 0; mi < 2; ++mi) {
#pragma unroll
                for (int nj = 0; nj < 4; ++nj) {
                    const uint32_t* bhp = &bh[nj >> 1][(nj & 1) * 2];
                    const uint32_t* blp = &bl[nj >> 1][(nj & 1) * 2];
                    mma_bf16(acc[mi][nj], ah[mi], bhp);
                    mma_bf16(acc[mi][nj], ah[mi], blp);
                    mma_bf16(acc[mi][nj], al[mi], bhp);
                }
            }
        }
    }

    // ---- epilogue: c-frag (row lane/4 (+8), col (lane&3)*2 (+1)) ----
#pragma unroll
    for (int mi = 0; mi < 2; ++mi) {
#pragma unroll
        for (int nj = 0; nj < 4; ++nj) {
            int rg = row0 + wm * 32 + mi * 16 + (lane >> 2);
            int cg = n0 + wn * 32 + nj * 8 + (lane & 3) * 2;
            float2 v0 = make_float2(acc[mi][nj][0], acc[mi][nj][1]);
            float2 v1 = make_float2(acc[mi][nj][2], acc[mi][nj][3]);
            if (Res) {
                float2 r0 = *(const float2*)&Res[(size_t)rg * DM_ + cg];
                float2 r1 = *(const float2*)&Res[(size_t)(rg + 8) * DM_ + cg];
                v0.x += r0.x; v0.y += r0.y;
                v1.x += r1.x; v1.y += r1.y;
            }
            *(float2*)&C[(size_t)rg * DM_ + cg]       = v0;
            *(float2*)&C[(size_t)(rg + 8) * DM_ + cg] = v1;
        }
    }
}

// =====================================================================
// Scores: attn[bh,q,k] = (Qh q . Kh k)/8, masked -1e9 (unchanged)
// =====================================================================
__global__ __launch_bounds__(256) void scores_kernel(
    const float* __restrict__ Q, const float* __restrict__ Kp,
    const unsigned char* __restrict__ mask_u8, float* __restrict__ attn)
{
    __shared__ float Qt[64][68];
    __shared__ float Kt[64][68];

    const int bh = blockIdx.z;
    const int b  = bh >> 4;
    const int h  = bh & 15;
    const int q0 = blockIdx.y * 64;
    const int k0 = blockIdx.x * 64;
    const int tid = threadIdx.x;
    const int mode = g_maskmode;
    const int*   mask_i32 = (const int*)mask_u8;
    const float* mask_f32 = (const float*)mask_u8;

    for (int i = tid; i < 64 * 16; i += 256) {
        int r  = i >> 4;
        int d4 = (i & 15) * 4;
        float4 qv = *(const float4*)&Q[((size_t)(b * S_ + q0 + r)) * DM_ + h * DK_ + d4];
        Qt[d4 + 0][r] = qv.x; Qt[d4 + 1][r] = qv.y;
        Qt[d4 + 2][r] = qv.z; Qt[d4 + 3][r] = qv.w;
        float4 kv = *(const float4*)&Kp[((size_t)(b * S_ + k0 + r)) * DM_ + h * DK_ + d4];
        Kt[d4 + 0][r] = kv.x; Kt[d4 + 1][r] = kv.y;
        Kt[d4 + 2][r] = kv.z; Kt[d4 + 3][r] = kv.w;
    }
    __syncthreads();

    const int tx = tid & 15;
    const int ty = tid >> 4;
    float acc[4][4];
#pragma unroll
    for (int i = 0; i < 4; i++)
#pragma unroll
        for (int j = 0; j < 4; j++) acc[i][j] = 0.f;

#pragma unroll
    for (int d = 0; d < 64; ++d) {
        float4 qv = *(const float4*)&Qt[d][ty * 4];
        float4 kv = *(const float4*)&Kt[d][tx * 4];
        float qm[4] = {qv.x, qv.y, qv.z, qv.w};
        float kn[4] = {kv.x, kv.y, kv.z, kv.w};
#pragma unroll
        for (int i = 0; i < 4; i++)
#pragma unroll
            for (int j = 0; j < 4; j++) acc[i][j] += qm[i] * kn[j];
    }

#pragma unroll
    for (int i = 0; i < 4; i++) {
        int qg = q0 + ty * 4 + i;
#pragma unroll
        for (int j = 0; j < 4; j++) {
            int kg = k0 + tx * 4 + j;
            float s = acc[i][j] * 0.125f;
            size_t midx = ((size_t)b * S_ + qg) * S_ + kg;
            bool masked;
            if (mode == 0)      masked = mask_u8[midx] != 0;
            else if (mode == 1) masked = mask_i32[midx] != 0;
            else                masked = mask_f32[midx] != 0.0f;
            attn[((size_t)bh * S_ + qg) * S_ + kg] = masked ? -1e9f : s;
        }
    }
}

// =====================================================================
// Row softmax over 2048 (unchanged)
// =====================================================================
__global__ __launch_bounds__(256) void softmax_kernel(float* __restrict__ attn)
{
    const int tid = threadIdx.x;
    float* p = attn + (size_t)blockIdx.x * S_;
    const int warp = tid >> 5, lane = tid & 31;
    __shared__ float red[8];

    float v[8];
#pragma unroll
    for (int j = 0; j < 8; j++) v[j] = p[tid + j * 256];

    float m = v[0];
#pragma unroll
    for (int j = 1; j < 8; j++) m = fmaxf(m, v[j]);
#pragma unroll
    for (int o = 16; o > 0; o >>= 1) m = fmaxf(m, __shfl_xor_sync(0xffffffffu, m, o));
    if (lane == 0) red[warp] = m;
    __syncthreads();
    if (tid == 0) {
        float t = red[0];
#pragma unroll
        for (int w = 1; w < 8; w++) t = fmaxf(t, red[w]);
        red[0] = t;
    }
    __syncthreads();
    m = red[0];

    float s = 0.f;
#pragma unroll
    for (int j = 0; j < 8; j++) { v[j] = __expf(v[j] - m); s += v[j]; }
#pragma unroll
    for (int o = 16; o > 0; o >>= 1) s += __shfl_xor_sync(0xffffffffu, s, o);
    __syncthreads();
    if (lane == 0) red[warp] = s;
    __syncthreads();
    if (tid == 0) {
        float t = 0.f;
#pragma unroll
        for (int w = 0; w < 8; w++) t += red[w];
        red[0] = t;
    }
    __syncthreads();
    float inv = 1.0f / red[0];

#pragma unroll
    for (int j = 0; j < 8; j++) p[tid + j * 256] = v[j] * inv;
}

// =====================================================================
// Context (unchanged)
// =====================================================================
__global__ __launch_bounds__(256) void ctx_kernel(
    const float* __restrict__ attn, const float* __restrict__ V,
    float* __restrict__ ctx)
{
    __shared__ float At[64][68];
    __shared__ float Vs[64][68];

    const int bh = blockIdx.y;
    const int b  = bh >> 4;
    const int h  = bh & 15;
    const int q0 = blockIdx.x * 64;
    const int tid = threadIdx.x;
    const int tx = tid & 15;
    const int ty = tid >> 4;

    float acc[4][4];
#pragma unroll
    for (int i = 0; i < 4; i++)
#pragma unroll
        for (int j = 0; j < 4; j++) acc[i][j] = 0.f;

    for (int kt = 0; kt < S_; kt += 64) {
        for (int i = tid; i < 64 * 16; i += 256) {
            int r  = i >> 4;
            int c4 = (i & 15) * 4;
            float4 av = *(const float4*)&attn[((size_t)bh * S_ + q0 + r) * S_ + kt + c4];
            At[c4 + 0][r] = av.x; At[c4 + 1][r] = av.y;
            At[c4 + 2][r] = av.z; At[c4 + 3][r] = av.w;
            float4 vv = *(const float4*)&V[((size_t)(b * S_ + kt + r)) * DM_ + h * DK_ + c4];
            *(float4*)&Vs[r][c4] = vv;
        }
        __syncthreads();

#pragma unroll
        for (int k = 0; k < 64; ++k) {
            float4 av = *(const float4*)&At[k][ty * 4];
            float4 vv = *(const float4*)&Vs[k][tx * 4];
            float am[4] = {av.x, av.y, av.z, av.w};
            float vn[4] = {vv.x, vv.y, vv.z, vv.w};
#pragma unroll
            for (int i = 0; i < 4; i++)
#pragma unroll
                for (int j = 0; j < 4; j++) acc[i][j] += am[i] * vn[j];
        }
        __syncthreads();
    }

#pragma unroll
    for (int i = 0; i < 4; i++) {
        int qg = q0 + ty * 4 + i;
#pragma unroll
        for (int j = 0; j < 4; j++) {
            int dv = tx * 4 + j;
            ctx[((size_t)(b * S_ + qg)) * DM_ + h * DK_ + dv] = acc[i][j];
        }
    }
}

// =====================================================================
// LayerNorm (unchanged)
// =====================================================================
__global__ __launch_bounds__(256) void ln_kernel(
    const float* __restrict__ y, float* __restrict__ out)
{
    const int tid = threadIdx.x;
    const float* p = y + (size_t)blockIdx.x * DM_;
    float* o = out + (size_t)blockIdx.x * DM_;
    const int warp = tid >> 5, lane = tid & 31;
    __shared__ float red[8];

    float v[4];
#pragma unroll
    for (int j = 0; j < 4; j++) v[j] = p[tid + j * 256];

    float s = v[0] + v[1] + v[2] + v[3];
#pragma unroll
    for (int o2 = 16; o2 > 0; o2 >>= 1) s += __shfl_xor_sync(0xffffffffu, s, o2);
    if (lane == 0) red[warp] = s;
    __syncthreads();
    if (tid == 0) {
        float t = 0.f;
#pragma unroll
        for (int w = 0; w < 8; w++) t += red[w];
        red[0] = t;
    }
    __syncthreads();
    float mu = red[0] * (1.0f / DM_);

    float sq = 0.f;
#pragma unroll
    for (int j = 0; j < 4; j++) { float d = v[j] - mu; sq += d * d; }
#pragma unroll
    for (int o2 = 16; o2 > 0; o2 >>= 1) sq += __shfl_xor_sync(0xffffffffu, sq, o2);
    __syncthreads();
    if (lane == 0) red[warp] = sq;
    __syncthreads();
    if (tid == 0) {
        float t = 0.f;
#pragma unroll
        for (int w = 0; w < 8; w++) t += red[w];
        red[0] = t;
    }
    __syncthreads();
    float inv = rsqrtf(red[0] * (1.0f / DM_) + 1e-5f);

#pragma unroll
    for (int j = 0; j < 4; j++) o[tid + j * 256] = (v[j] - mu) * inv;
}

// =====================================================================
// Launch
// =====================================================================
extern "C" void kernel_launch(void* const* d_in, const int* in_sizes, int n_in,
                              void* d_out, int out_size)
{
    const float* inQ = (const float*)d_in[0];
    const float* inK = (const float*)d_in[1];
    const float* inV = (const float*)d_in[2];
    const unsigned char* mask = (const unsigned char*)d_in[3];
    const float* WQ = (const float*)d_in[4];
    const float* WK = (const float*)d_in[5];
    const float* WV = (const float*)d_in[6];
    const float* WO = (const float*)d_in[7];
    float* out = (float*)d_out;

    float *Qp, *Kp, *Vp, *Cp, *Yp, *Ap;
    cudaGetSymbolAddress((void**)&Qp, g_Q);
    cudaGetSymbolAddress((void**)&Kp, g_K);
    cudaGetSymbolAddress((void**)&Vp, g_V);
    cudaGetSymbolAddress((void**)&Cp, g_ctx);
    cudaGetSymbolAddress((void**)&Yp, g_y);
    cudaGetSymbolAddress((void**)&Ap, g_attn);

    float* attn = ((long long)out_size >= OUT_ELEMS + ATTN_ELEMS) ? (out + OUT_ELEMS) : Ap;

    cudaFuncSetAttribute(mma_gemm, cudaFuncAttributeMaxDynamicSharedMemorySize,
                         MMA_SMEM_BYTES);

    detect_mask_kernel<<<1, 256>>>(mask);

    dim3 tc_grid(DM_ / 64, M_ / 128);   // (16, 32)
    mma_gemm<<<tc_grid, 256, MMA_SMEM_BYTES>>>(inQ, WQ, nullptr, Qp);
    mma_gemm<<<tc_grid, 256, MMA_SMEM_BYTES>>>(inK, WK, nullptr, Kp);
    mma_gemm<<<tc_grid, 256, MMA_SMEM_BYTES>>>(inV, WV, nullptr, Vp);

    scores_kernel<<<dim3(S_ / 64, S_ / 64, B_ * H_), 256>>>(Qp, Kp, mask, attn);
    softmax_kernel<<<B_ * H_ * S_, 256>>>(attn);
    ctx_kernel<<<dim3(S_ / 64, B_ * H_), 256>>>(attn, Vp, Cp);

    mma_gemm<<<tc_grid, 256, MMA_SMEM_BYTES>>>(Cp, WO, inQ, Yp);
    ln_kernel<<<M_, 256>>>(Yp, out);
}

// round 5
// speedup vs baseline: 2.1911x; 1.7119x over previous
#include <cuda_runtime.h>
#include <cuda_bf16.h>
#include <cstddef>
#include <cstdint>

// Problem constants
#define B_   2
#define S_   2048
#define DM_  1024
#define H_   16
#define DK_  64
#define M_   (B_ * S_)             // 4096 rows
#define OUT_ELEMS  ((long long)M_ * DM_)                 // 4,194,304
#define ATTN_ELEMS ((long long)B_ * H_ * S_ * S_)        // 134,217,728

// ---------------- scratch (device globals) ----------------
__device__ float g_Q[M_ * DM_];
__device__ float g_K[M_ * DM_];
__device__ float g_V[M_ * DM_];
__device__ float g_ctx[M_ * DM_];
__device__ float g_y[M_ * DM_];
__device__ float g_attn[(size_t)B_ * H_ * S_ * S_];
__device__ int   g_maskmode;   // 0=uint8, 1=int32, 2=float32

// =====================================================================
// Mask storage-format detection (proven)
// =====================================================================
__global__ void detect_mask_kernel(const unsigned char* __restrict__ m)
{
    __shared__ int cnt[4];
    if (threadIdx.x < 4) cnt[threadIdx.x] = 0;
    __syncthreads();
    for (int i = threadIdx.x; i < 65536; i += blockDim.x)
        if (m[i]) atomicAdd(&cnt[i & 3], 1);
    __syncthreads();
    if (threadIdx.x == 0) {
        int mode;
        if (cnt[1] > 0)      mode = 0;
        else if (cnt[0] > 0) mode = 1;
        else                 mode = 2;
        g_maskmode = mode;
    }
}

// =====================================================================
// mma.sync helpers
// =====================================================================
__device__ __forceinline__ void ldsm_x4(uint32_t* r, uint32_t addr) {
    asm volatile("ldmatrix.sync.aligned.m8n8.x4.shared.b16 {%0,%1,%2,%3}, [%4];"
                 : "=r"(r[0]), "=r"(r[1]), "=r"(r[2]), "=r"(r[3]) : "r"(addr));
}
__device__ __forceinline__ void ldsm_x4t(uint32_t* r, uint32_t addr) {
    asm volatile("ldmatrix.sync.aligned.m8n8.x4.trans.shared.b16 {%0,%1,%2,%3}, [%4];"
                 : "=r"(r[0]), "=r"(r[1]), "=r"(r[2]), "=r"(r[3]) : "r"(addr));
}
__device__ __forceinline__ void mma_bf16(float* c, const uint32_t* a, const uint32_t* b) {
    asm volatile(
        "mma.sync.aligned.m16n8k16.row.col.f32.bf16.bf16.f32 "
        "{%0,%1,%2,%3}, {%4,%5,%6,%7}, {%8,%9}, {%0,%1,%2,%3};"
        : "+f"(c[0]), "+f"(c[1]), "+f"(c[2]), "+f"(c[3])
        : "r"(a[0]), "r"(a[1]), "r"(a[2]), "r"(a[3]), "r"(b[0]), "r"(b[1]));
}

__device__ __forceinline__ void split_bf16(float x, __nv_bfloat16& h, __nv_bfloat16& l) {
    h = __float2bfloat16_rn(x);
    l = __float2bfloat16_rn(x - __bfloat162float(h));
}

// =====================================================================
// Generalized mma.sync split-bf16 GEMM.
//   IS_CTX=false:  C[4096,1024] = A[4096,1024]@B[1024,1024] (+Res)
//                  grid (16 n-tiles, 32 m-tiles, 1)
//   IS_CTX=true :  ctx: per bh slice, C[2048,64] = attn[2048,2048]@V[2048,64]
//                  grid (1, 16 m-tiles, 32 bh)
// Block tile 128(M)x64(N), 8 warps (4x2), warp tile 32x32, K-chunk 64.
// =====================================================================
#define PADK 72
#define SM_AH 0
#define SM_AL (128 * PADK * 2)
#define SM_BH (2 * 128 * PADK * 2)
#define SM_BL (2 * 128 * PADK * 2 + 64 * PADK * 2)
#define MMA_SMEM_BYTES (2 * 128 * PADK * 2 + 2 * 64 * PADK * 2)   // 55296

template<bool IS_CTX>
__global__ __launch_bounds__(256) void mma_gemm_t(
    const float* __restrict__ A, const float* __restrict__ Bm,
    const float* __restrict__ Res, float* __restrict__ C)
{
    extern __shared__ __align__(16) char dsm[];
    const uint32_t sbase = (uint32_t)__cvta_generic_to_shared(dsm);

    const int tid  = threadIdx.x;
    const int lane = tid & 31;
    const int warp = tid >> 5;
    const int wm   = warp & 3;
    const int wn   = warp >> 2;
    const int row0 = blockIdx.y * 128;
    const int n0   = blockIdx.x * 64;

    int lda, ldb, ldc, kLen;
    if (IS_CTX) {
        const int bh = blockIdx.z;
        const int b  = bh >> 4;
        const int h  = bh & 15;
        A += (size_t)bh * S_ * S_;
        Bm += (size_t)b * S_ * DM_ + h * DK_;
        C += (size_t)b * S_ * DM_ + h * DK_;
        lda = S_; ldb = DM_; ldc = DM_; kLen = S_;
    } else {
        lda = DM_; ldb = DM_; ldc = DM_; kLen = DM_;
    }

    float acc[2][4][4];
#pragma unroll
    for (int i = 0; i < 2; i++)
#pragma unroll
        for (int j = 0; j < 4; j++)
#pragma unroll
            for (int k = 0; k < 4; k++) acc[i][j][k] = 0.f;

    uint32_t aoff[2], boff[2];
#pragma unroll
    for (int mi = 0; mi < 2; ++mi)
        aoff[mi] = (uint32_t)((wm * 32 + mi * 16 + (lane & 15)) * PADK + (lane >> 4) * 8);
#pragma unroll
    for (int njp = 0; njp < 2; ++njp)
        boff[njp] = (uint32_t)((((lane >> 3) & 1) * 8 + (lane & 7)) * PADK
                               + wn * 32 + njp * 16 + (lane >> 4) * 8);

    for (int c = 0; c < kLen / 64; ++c) {
        const int k0 = c * 64;

        float4 av[8];
#pragma unroll
        for (int i = 0; i < 8; ++i) {
            int idx = tid + i * 256;
            int r  = idx >> 4;
            int kc = (idx & 15) * 4;
            av[i] = *(const float4*)&A[(size_t)(row0 + r) * lda + k0 + kc];
        }
        float4 bv[4];
#pragma unroll
        for (int i = 0; i < 4; ++i) {
            int idx = tid + i * 256;
            int kr = idx >> 4;
            int nc = (idx & 15) * 4;
            bv[i] = *(const float4*)&Bm[(size_t)(k0 + kr) * ldb + n0 + nc];
        }

        if (c > 0) __syncthreads();

#pragma unroll
        for (int i = 0; i < 8; ++i) {
            int idx = tid + i * 256;
            int r  = idx >> 4;
            int kc = (idx & 15) * 4;
            uint32_t eo = (uint32_t)(r * PADK + kc) * 2;
            __nv_bfloat16 h0, h1, h2, h3, l0, l1, l2, l3;
            split_bf16(av[i].x, h0, l0); split_bf16(av[i].y, h1, l1);
            split_bf16(av[i].z, h2, l2); split_bf16(av[i].w, h3, l3);
            *(__nv_bfloat162*)(dsm + SM_AH + eo)     = __halves2bfloat162(h0, h1);
            *(__nv_bfloat162*)(dsm + SM_AH + eo + 4) = __halves2bfloat162(h2, h3);
            *(__nv_bfloat162*)(dsm + SM_AL + eo)     = __halves2bfloat162(l0, l1);
            *(__nv_bfloat162*)(dsm + SM_AL + eo + 4) = __halves2bfloat162(l2, l3);
        }
#pragma unroll
        for (int i = 0; i < 4; ++i) {
            int idx = tid + i * 256;
            int kr = idx >> 4;
            int nc = (idx & 15) * 4;
            uint32_t eo = (uint32_t)(kr * PADK + nc) * 2;
            __nv_bfloat16 h0, h1, h2, h3, l0, l1, l2, l3;
            split_bf16(bv[i].x, h0, l0); split_bf16(bv[i].y, h1, l1);
            split_bf16(bv[i].z, h2, l2); split_bf16(bv[i].w, h3, l3);
            *(__nv_bfloat162*)(dsm + SM_BH + eo)     = __halves2bfloat162(h0, h1);
            *(__nv_bfloat162*)(dsm + SM_BH + eo + 4) = __halves2bfloat162(h2, h3);
            *(__nv_bfloat162*)(dsm + SM_BL + eo)     = __halves2bfloat162(l0, l1);
            *(__nv_bfloat162*)(dsm + SM_BL + eo + 4) = __halves2bfloat162(l2, l3);
        }
        __syncthreads();

#pragma unroll
        for (int ks = 0; ks < 4; ++ks) {
            uint32_t ah[2][4], al[2][4], bh[2][4], bl[2][4];
#pragma unroll
            for (int mi = 0; mi < 2; ++mi) {
                uint32_t eo = (aoff[mi] + ks * 16) * 2;
                ldsm_x4(ah[mi], sbase + SM_AH + eo);
                ldsm_x4(al[mi], sbase + SM_AL + eo);
            }
#pragma unroll
            for (int njp = 0; njp < 2; ++njp) {
                uint32_t eo = (boff[njp] + ks * 16 * PADK) * 2;
                ldsm_x4t(bh[njp], sbase + SM_BH + eo);
                ldsm_x4t(bl[njp], sbase + SM_BL + eo);
            }
#pragma unroll
            for (int mi = 0; mi < 2; ++mi) {
#pragma unroll
                for (int nj = 0; nj < 4; ++nj) {
                    const uint32_t* bhp = &bh[nj >> 1][(nj & 1) * 2];
                    const uint32_t* blp = &bl[nj >> 1][(nj & 1) * 2];
                    mma_bf16(acc[mi][nj], ah[mi], bhp);
                    mma_bf16(acc[mi][nj], ah[mi], blp);
                    mma_bf16(acc[mi][nj], al[mi], bhp);
                }
            }
        }
    }

#pragma unroll
    for (int mi = 0; mi < 2; ++mi) {
#pragma unroll
        for (int nj = 0; nj < 4; ++nj) {
            int rg = row0 + wm * 32 + mi * 16 + (lane >> 2);
            int cg = n0 + wn * 32 + nj * 8 + (lane & 3) * 2;
            float2 v0 = make_float2(acc[mi][nj][0], acc[mi][nj][1]);
            float2 v1 = make_float2(acc[mi][nj][2], acc[mi][nj][3]);
            if (Res) {
                float2 r0 = *(const float2*)&Res[(size_t)rg * ldc + cg];
                float2 r1 = *(const float2*)&Res[(size_t)(rg + 8) * ldc + cg];
                v0.x += r0.x; v0.y += r0.y;
                v1.x += r1.x; v1.y += r1.y;
            }
            *(float2*)&C[(size_t)rg * ldc + cg]       = v0;
            *(float2*)&C[(size_t)(rg + 8) * ldc + cg] = v1;
        }
    }
}

// =====================================================================
// Scores via mma.sync split-bf16:
//   attn[bh,q,k] = masked ? -1e9 : (Q_h q . K_h k) / 8
// Block tile 128q x 128k, 8 warps (4x2), warp 32q x 64k, d=64 resident.
// Q tile [q][d] row-major -> A frags (ldsm non-trans).
// K tile [k][d] row-major = [n][k_inner]  -> B frags (ldsm non-trans,
//   tile order: k-half from lane>>3&1, n-half from lane>>4).
// =====================================================================
#define SC_QH 0
#define SC_QL (128 * PADK * 2)
#define SC_KH (2 * 128 * PADK * 2)
#define SC_KL (3 * 128 * PADK * 2)
#define SC_SMEM_BYTES (4 * 128 * PADK * 2)   // 73728

__global__ __launch_bounds__(256) void scores_mma(
    const float* __restrict__ Q, const float* __restrict__ Kp,
    const unsigned char* __restrict__ mask_u8, float* __restrict__ attn)
{
    extern __shared__ __align__(16) char dsm[];
    const uint32_t sbase = (uint32_t)__cvta_generic_to_shared(dsm);

    const int bh = blockIdx.z;
    const int b  = bh >> 4;
    const int h  = bh & 15;
    const int q0 = blockIdx.y * 128;
    const int k0 = blockIdx.x * 128;
    const int tid  = threadIdx.x;
    const int lane = tid & 31;
    const int warp = tid >> 5;
    const int wm   = warp & 3;    // q: 4 x 32
    const int wn   = warp >> 2;   // k: 2 x 64
    const int mode = g_maskmode;

    // ---- load Q/K tiles (128 rows x 64 d fp32), split to hi/lo bf16 ----
    float4 qv[8], kv[8];
#pragma unroll
    for (int i = 0; i < 8; ++i) {
        int idx = tid + i * 256;
        int r  = idx >> 4;
        int d4 = (idx & 15) * 4;
        qv[i] = *(const float4*)&Q[((size_t)(b * S_ + q0 + r)) * DM_ + h * DK_ + d4];
        kv[i] = *(const float4*)&Kp[((size_t)(b * S_ + k0 + r)) * DM_ + h * DK_ + d4];
    }
#pragma unroll
    for (int i = 0; i < 8; ++i) {
        int idx = tid + i * 256;
        int r  = idx >> 4;
        int d4 = (idx & 15) * 4;
        uint32_t eo = (uint32_t)(r * PADK + d4) * 2;
        __nv_bfloat16 h0, h1, h2, h3, l0, l1, l2, l3;
        split_bf16(qv[i].x, h0, l0); split_bf16(qv[i].y, h1, l1);
        split_bf16(qv[i].z, h2, l2); split_bf16(qv[i].w, h3, l3);
        *(__nv_bfloat162*)(dsm + SC_QH + eo)     = __halves2bfloat162(h0, h1);
        *(__nv_bfloat162*)(dsm + SC_QH + eo + 4) = __halves2bfloat162(h2, h3);
        *(__nv_bfloat162*)(dsm + SC_QL + eo)     = __halves2bfloat162(l0, l1);
        *(__nv_bfloat162*)(dsm + SC_QL + eo + 4) = __halves2bfloat162(l2, l3);
        split_bf16(kv[i].x, h0, l0); split_bf16(kv[i].y, h1, l1);
        split_bf16(kv[i].z, h2, l2); split_bf16(kv[i].w, h3, l3);
        *(__nv_bfloat162*)(dsm + SC_KH + eo)     = __halves2bfloat162(h0, h1);
        *(__nv_bfloat162*)(dsm + SC_KH + eo + 4) = __halves2bfloat162(h2, h3);
        *(__nv_bfloat162*)(dsm + SC_KL + eo)     = __halves2bfloat162(l0, l1);
        *(__nv_bfloat162*)(dsm + SC_KL + eo + 4) = __halves2bfloat162(l2, l3);
    }
    __syncthreads();

    float acc[2][8][4];
#pragma unroll
    for (int i = 0; i < 2; i++)
#pragma unroll
        for (int j = 0; j < 8; j++)
#pragma unroll
            for (int k = 0; k < 4; k++) acc[i][j][k] = 0.f;

    uint32_t aoff[2];
#pragma unroll
    for (int mi = 0; mi < 2; ++mi)
        aoff[mi] = (uint32_t)((wm * 32 + mi * 16 + (lane & 15)) * PADK + (lane >> 4) * 8);
    // B (non-trans): n from addressed row, k from 16B column offset
    const uint32_t bbase = (uint32_t)((wn * 64 + (lane >> 4) * 8 + (lane & 7)) * PADK
                                      + ((lane >> 3) & 1) * 8);

#pragma unroll
    for (int ks = 0; ks < 4; ++ks) {
        uint32_t ah[2][4], al[2][4], bh[4][4], bl[4][4];
#pragma unroll
        for (int mi = 0; mi < 2; ++mi) {
            uint32_t eo = (aoff[mi] + ks * 16) * 2;
            ldsm_x4(ah[mi], sbase + SC_QH + eo);
            ldsm_x4(al[mi], sbase + SC_QL + eo);
        }
#pragma unroll
        for (int j = 0; j < 4; ++j) {
            uint32_t eo = (bbase + j * 16 * PADK + ks * 16) * 2;
            ldsm_x4(bh[j], sbase + SC_KH + eo);
            ldsm_x4(bl[j], sbase + SC_KL + eo);
        }
#pragma unroll
        for (int mi = 0; mi < 2; ++mi) {
#pragma unroll
            for (int nj = 0; nj < 8; ++nj) {
                const uint32_t* bhp = &bh[nj >> 1][(nj & 1) * 2];
                const uint32_t* blp = &bl[nj >> 1][(nj & 1) * 2];
                mma_bf16(acc[mi][nj], ah[mi], bhp);
                mma_bf16(acc[mi][nj], ah[mi], blp);
                mma_bf16(acc[mi][nj], al[mi], bhp);
            }
        }
    }

    // ---- epilogue: scale 1/8, mask, write ----
    const int*   mask_i32 = (const int*)mask_u8;
    const float* mask_f32 = (const float*)mask_u8;
#pragma unroll
    for (int mi = 0; mi < 2; ++mi) {
#pragma unroll
        for (int nj = 0; nj < 8; ++nj) {
            int qg = q0 + wm * 32 + mi * 16 + (lane >> 2);
            int kg = k0 + wn * 64 + nj * 8 + (lane & 3) * 2;
#pragma unroll
            for (int rr = 0; rr < 2; ++rr) {
                int qr = qg + rr * 8;
                float s0 = acc[mi][nj][rr * 2 + 0] * 0.125f;
                float s1 = acc[mi][nj][rr * 2 + 1] * 0.125f;
                size_t midx = ((size_t)b * S_ + qr) * S_ + kg;
                bool m0, m1;
                if (mode == 1) {
                    int2 mv = *(const int2*)&mask_i32[midx];
                    m0 = mv.x != 0; m1 = mv.y != 0;
                } else if (mode == 0) {
                    m0 = mask_u8[midx] != 0; m1 = mask_u8[midx + 1] != 0;
                } else {
                    float2 mv = *(const float2*)&mask_f32[midx];
                    m0 = mv.x != 0.0f; m1 = mv.y != 0.0f;
                }
                float2 v = make_float2(m0 ? -1e9f : s0, m1 ? -1e9f : s1);
                *(float2*)&attn[((size_t)bh * S_ + qr) * S_ + kg] = v;
            }
        }
    }
}

// =====================================================================
// Row softmax over 2048 (unchanged)
// =====================================================================
__global__ __launch_bounds__(256) void softmax_kernel(float* __restrict__ attn)
{
    const int tid = threadIdx.x;
    float* p = attn + (size_t)blockIdx.x * S_;
    const int warp = tid >> 5, lane = tid & 31;
    __shared__ float red[8];

    float v[8];
#pragma unroll
    for (int j = 0; j < 8; j++) v[j] = p[tid + j * 256];

    float m = v[0];
#pragma unroll
    for (int j = 1; j < 8; j++) m = fmaxf(m, v[j]);
#pragma unroll
    for (int o = 16; o > 0; o >>= 1) m = fmaxf(m, __shfl_xor_sync(0xffffffffu, m, o));
    if (lane == 0) red[warp] = m;
    __syncthreads();
    if (tid == 0) {
        float t = red[0];
#pragma unroll
        for (int w = 1; w < 8; w++) t = fmaxf(t, red[w]);
        red[0] = t;
    }
    __syncthreads();
    m = red[0];

    float s = 0.f;
#pragma unroll
    for (int j = 0; j < 8; j++) { v[j] = __expf(v[j] - m); s += v[j]; }
#pragma unroll
    for (int o = 16; o > 0; o >>= 1) s += __shfl_xor_sync(0xffffffffu, s, o);
    __syncthreads();
    if (lane == 0) red[warp] = s;
    __syncthreads();
    if (tid == 0) {
        float t = 0.f;
#pragma unroll
        for (int w = 0; w < 8; w++) t += red[w];
        red[0] = t;
    }
    __syncthreads();
    float inv = 1.0f / red[0];

#pragma unroll
    for (int j = 0; j < 8; j++) p[tid + j * 256] = v[j] * inv;
}

// =====================================================================
// LayerNorm (unchanged)
// =====================================================================
__global__ __launch_bounds__(256) void ln_kernel(
    const float* __restrict__ y, float* __restrict__ out)
{
    const int tid = threadIdx.x;
    const float* p = y + (size_t)blockIdx.x * DM_;
    float* o = out + (size_t)blockIdx.x * DM_;
    const int warp = tid >> 5, lane = tid & 31;
    __shared__ float red[8];

    float v[4];
#pragma unroll
    for (int j = 0; j < 4; j++) v[j] = p[tid + j * 256];

    float s = v[0] + v[1] + v[2] + v[3];
#pragma unroll
    for (int o2 = 16; o2 > 0; o2 >>= 1) s += __shfl_xor_sync(0xffffffffu, s, o2);
    if (lane == 0) red[warp] = s;
    __syncthreads();
    if (tid == 0) {
        float t = 0.f;
#pragma unroll
        for (int w = 0; w < 8; w++) t += red[w];
        red[0] = t;
    }
    __syncthreads();
    float mu = red[0] * (1.0f / DM_);

    float sq = 0.f;
#pragma unroll
    for (int j = 0; j < 4; j++) { float d = v[j] - mu; sq += d * d; }
#pragma unroll
    for (int o2 = 16; o2 > 0; o2 >>= 1) sq += __shfl_xor_sync(0xffffffffu, sq, o2);
    __syncthreads();
    if (lane == 0) red[warp] = sq;
    __syncthreads();
    if (tid == 0) {
        float t = 0.f;
#pragma unroll
        for (int w = 0; w < 8; w++) t += red[w];
        red[0] = t;
    }
    __syncthreads();
    float inv = rsqrtf(red[0] * (1.0f / DM_) + 1e-5f);

#pragma unroll
    for (int j = 0; j < 4; j++) o[tid + j * 256] = (v[j] - mu) * inv;
}

// =====================================================================
// Launch
// =====================================================================
extern "C" void kernel_launch(void* const* d_in, const int* in_sizes, int n_in,
                              void* d_out, int out_size)
{
    const float* inQ = (const float*)d_in[0];
    const float* inK = (const float*)d_in[1];
    const float* inV = (const float*)d_in[2];
    const unsigned char* mask = (const unsigned char*)d_in[3];
    const float* WQ = (const float*)d_in[4];
    const float* WK = (const float*)d_in[5];
    const float* WV = (const float*)d_in[6];
    const float* WO = (const float*)d_in[7];
    float* out = (float*)d_out;

    float *Qp, *Kp, *Vp, *Cp, *Yp, *Ap;
    cudaGetSymbolAddress((void**)&Qp, g_Q);
    cudaGetSymbolAddress((void**)&Kp, g_K);
    cudaGetSymbolAddress((void**)&Vp, g_V);
    cudaGetSymbolAddress((void**)&Cp, g_ctx);
    cudaGetSymbolAddress((void**)&Yp, g_y);
    cudaGetSymbolAddress((void**)&Ap, g_attn);

    float* attn = ((long long)out_size >= OUT_ELEMS + ATTN_ELEMS) ? (out + OUT_ELEMS) : Ap;

    cudaFuncSetAttribute(mma_gemm_t<false>, cudaFuncAttributeMaxDynamicSharedMemorySize,
                         MMA_SMEM_BYTES);
    cudaFuncSetAttribute(mma_gemm_t<true>, cudaFuncAttributeMaxDynamicSharedMemorySize,
                         MMA_SMEM_BYTES);
    cudaFuncSetAttribute(scores_mma, cudaFuncAttributeMaxDynamicSharedMemorySize,
                         SC_SMEM_BYTES);

    detect_mask_kernel<<<1, 256>>>(mask);

    dim3 proj_grid(DM_ / 64, M_ / 128);   // (16, 32)
    mma_gemm_t<false><<<proj_grid, 256, MMA_SMEM_BYTES>>>(inQ, WQ, nullptr, Qp);
    mma_gemm_t<false><<<proj_grid, 256, MMA_SMEM_BYTES>>>(inK, WK, nullptr, Kp);
    mma_gemm_t<false><<<proj_grid, 256, MMA_SMEM_BYTES>>>(inV, WV, nullptr, Vp);

    scores_mma<<<dim3(S_ / 128, S_ / 128, B_ * H_), 256, SC_SMEM_BYTES>>>(Qp, Kp, mask, attn);
    softmax_kernel<<<B_ * H_ * S_, 256>>>(attn);
    mma_gemm_t<true><<<dim3(1, S_ / 128, B_ * H_), 256, MMA_SMEM_BYTES>>>(attn, Vp, nullptr, Cp);

    mma_gemm_t<false><<<proj_grid, 256, MMA_SMEM_BYTES>>>(Cp, WO, inQ, Yp);
    ln_kernel<<<M_, 256>>>(Yp, out);
}